// round 2
// baseline (speedup 1.0000x reference)
#include <cuda_runtime.h>
#include <cuda_fp16.h>
#include <math.h>
#include <stdint.h>

#define S_LEN 512
#define B_SZ  64
#define H_DIM 1024
#define M_TOT (S_LEN * B_SZ)   // 32768 rows of the big GEMM
#define KDIM  H_DIM
#define NDIM  H_DIM

// ---------------- scratch (static device globals; no runtime allocation) ----------------
__device__ __half g_ench[M_TOT * H_DIM];   // enc pre-converted to fp16 (64MB)
__device__ __half g_Wh[H_DIM * H_DIM];     // Wa[:, H:2H] pre-converted (2MB), [n][k]
__device__ float  g_hb[B_SZ * H_DIM];      // hidden @ Wa1^T + ba   (64 x 1024)
__device__ float  g_attn_raw[M_TOT];       // sum_n relu(z+hb)*Ws   (S*B)
__device__ int    g_mask_mode;             // 0=none, 1=byte, 2=int32, 3=float32

// ---------------- kernel 0: zero scratch + detect mask dtype ----------------
__global__ void detect_and_zero(const unsigned char* __restrict__ mask_bytes) {
    for (int i = blockIdx.x * blockDim.x + threadIdx.x; i < M_TOT;
         i += gridDim.x * blockDim.x)
        g_attn_raw[i] = 0.0f;

    if (blockIdx.x == 0) {
        __shared__ int flag[4];
        if (threadIdx.x < 4) flag[threadIdx.x] = 0;
        __syncthreads();
        for (int i = threadIdx.x; i < B_SZ * S_LEN; i += blockDim.x) {
            if (mask_bytes[i]) atomicOr(&flag[i & 3], 1);
        }
        __syncthreads();
        if (threadIdx.x == 0) {
            int mode;
            if (flag[1])                mode = 1;
            else if (flag[0])           mode = 2;
            else if (flag[2] | flag[3]) mode = 3;
            else                        mode = 0;
            g_mask_mode = mode;
        }
    }
}

// ---------------- kernel 0b: pre-convert enc to fp16 ----------------
__global__ void convert_enc(const float* __restrict__ enc) {
    const int n4 = M_TOT * H_DIM / 4;
    for (int i = blockIdx.x * blockDim.x + threadIdx.x; i < n4;
         i += gridDim.x * blockDim.x) {
        float4 v = ((const float4*)enc)[i];
        __half2* dst = (__half2*)g_ench;
        dst[2 * i]     = __floats2half2_rn(v.x, v.y);
        dst[2 * i + 1] = __floats2half2_rn(v.z, v.w);
    }
}

// ---------------- kernel 0c: pre-convert Wa[:, H:2H] to fp16 ----------------
__global__ void convert_w(const float* __restrict__ Wa) {
    const int n4 = H_DIM * H_DIM / 4;   // 262144 float4s
    for (int i = blockIdx.x * blockDim.x + threadIdx.x; i < n4;
         i += gridDim.x * blockDim.x) {
        const int n  = i >> 8;          // row (256 float4 per row)
        const int kc = i & 255;
        float4 v = *(const float4*)(Wa + (size_t)n * (2 * H_DIM) + H_DIM + kc * 4);
        __half2* dst = (__half2*)(g_Wh + (size_t)n * H_DIM + kc * 4);
        dst[0] = __floats2half2_rn(v.x, v.y);
        dst[1] = __floats2half2_rn(v.z, v.w);
    }
}

// ---------------- kernel 1: hb[b,n] = hidden[b,:] . Wa[n,0:H] + ba[n] ----------------
// warp-per-n: Wa row held in registers, read once total.
__global__ void hb_kernel(const float* __restrict__ hidden,
                          const float* __restrict__ Wa,
                          const float* __restrict__ ba) {
    const int warp = threadIdx.x >> 5;
    const int lane = threadIdx.x & 31;
    const int n    = blockIdx.x * 8 + warp;  // grid 128 x 8 warps
    const float* wrow = Wa + (size_t)n * (2 * H_DIM);
    float w[32];
    #pragma unroll
    for (int i = 0; i < 32; i++) w[i] = wrow[lane + 32 * i];
    const float bias = ba[n];
    for (int b = 0; b < B_SZ; b++) {
        const float* h = hidden + b * H_DIM;
        float s = 0.0f;
        #pragma unroll
        for (int i = 0; i < 32; i++) s += w[i] * h[lane + 32 * i];
        #pragma unroll
        for (int o = 16; o; o >>= 1) s += __shfl_xor_sync(0xffffffffu, s, o);
        if (lane == 0) g_hb[b * H_DIM + n] = s + bias;
    }
}

// ---------------- kernel 2: fp16 GEMM (cp.async double-buffered) + relu + Ws reduce ----------------
#define BM 128
#define BN 128
#define BK 32
#define AST 40   // half-element row stride (32 + 8 pad: keeps 16B align, kills conflicts)
#define NT (KDIM / BK)   // 32 k-tiles

__global__ __launch_bounds__(256, 2)
void gemm_kernel(const float* __restrict__ Ws) {
    __shared__ __half As[2][BM * AST];
    __shared__ __half Bs[2][BN * AST];

    const int tid    = threadIdx.x;
    const int warp   = tid >> 5;
    const int lane   = tid & 31;
    const int warp_m = warp >> 2;   // 0..1  (64-row slab)
    const int warp_n = warp & 3;    // 0..3  (32-col slab)
    const int m0 = blockIdx.y * BM;
    const int n0 = blockIdx.x * BN;

    float c[4][4][4];
    #pragma unroll
    for (int a = 0; a < 4; a++)
        #pragma unroll
        for (int bq = 0; bq < 4; bq++)
            #pragma unroll
            for (int d = 0; d < 4; d++) c[a][bq][d] = 0.0f;

    // cp.async loaders: 256 threads; per tile (128 rows x 32 halfs = 64B/row = 4 chunks)
    // 512 chunks per tile -> 2 chunks/thread per tile.
    const int lrow = tid >> 1;                 // 0..127
    const int lcol = (tid & 1) * 16;           // halfs: chunk pair base (2x 16B)
    const __half* Ag = g_ench + (size_t)(m0 + lrow) * KDIM + lcol;
    const __half* Bg = g_Wh   + (size_t)(n0 + lrow) * KDIM + lcol;
    const uint32_t sA = (uint32_t)__cvta_generic_to_shared(&As[0][0]) + (lrow * AST + lcol) * 2;
    const uint32_t sB = (uint32_t)__cvta_generic_to_shared(&Bs[0][0]) + (lrow * AST + lcol) * 2;
    const uint32_t stageBytes = BM * AST * 2;  // 10240

    #define ISSUE_STAGE(s, k0)                                                     \
        do {                                                                       \
            asm volatile("cp.async.cg.shared.global [%0], [%1], 16;\n"             \
                         :: "r"(sA + (s) * stageBytes), "l"(Ag + (k0)));           \
            asm volatile("cp.async.cg.shared.global [%0], [%1], 16;\n"             \
                         :: "r"(sA + (s) * stageBytes + 16), "l"(Ag + (k0) + 8));  \
            asm volatile("cp.async.cg.shared.global [%0], [%1], 16;\n"             \
                         :: "r"(sB + (s) * stageBytes), "l"(Bg + (k0)));           \
            asm volatile("cp.async.cg.shared.global [%0], [%1], 16;\n"             \
                         :: "r"(sB + (s) * stageBytes + 16), "l"(Bg + (k0) + 8));  \
            asm volatile("cp.async.commit_group;\n");                              \
        } while (0)

    ISSUE_STAGE(0, 0);

    for (int kt = 0; kt < NT; kt++) {
        const int cur = kt & 1;
        if (kt + 1 < NT) {
            ISSUE_STAGE((kt + 1) & 1, (kt + 1) * BK);
            asm volatile("cp.async.wait_group 1;\n");
        } else {
            asm volatile("cp.async.wait_group 0;\n");
        }
        __syncthreads();

        #pragma unroll
        for (int kk = 0; kk < BK; kk += 16) {
            uint32_t afr[4][4], bfr[4][2];
            #pragma unroll
            for (int mf = 0; mf < 4; mf++) {
                const __half* base = &As[cur][(warp_m * 64 + mf * 16 + (lane >> 2)) * AST];
                const int col = (lane & 3) * 2 + kk;
                afr[mf][0] = *(const uint32_t*)(base + col);
                afr[mf][1] = *(const uint32_t*)(base + 8 * AST + col);
                afr[mf][2] = *(const uint32_t*)(base + col + 8);
                afr[mf][3] = *(const uint32_t*)(base + 8 * AST + col + 8);
            }
            #pragma unroll
            for (int nf = 0; nf < 4; nf++) {
                const __half* base = &Bs[cur][(warp_n * 32 + nf * 8 + (lane >> 2)) * AST];
                const int col = (lane & 3) * 2 + kk;
                bfr[nf][0] = *(const uint32_t*)(base + col);
                bfr[nf][1] = *(const uint32_t*)(base + col + 8);
            }
            #pragma unroll
            for (int mf = 0; mf < 4; mf++)
                #pragma unroll
                for (int nf = 0; nf < 4; nf++)
                    asm volatile(
                        "mma.sync.aligned.m16n8k16.row.col.f32.f16.f16.f32 "
                        "{%0,%1,%2,%3}, {%4,%5,%6,%7}, {%8,%9}, {%0,%1,%2,%3};\n"
                        : "+f"(c[mf][nf][0]), "+f"(c[mf][nf][1]),
                          "+f"(c[mf][nf][2]), "+f"(c[mf][nf][3])
                        : "r"(afr[mf][0]), "r"(afr[mf][1]),
                          "r"(afr[mf][2]), "r"(afr[mf][3]),
                          "r"(bfr[nf][0]), "r"(bfr[nf][1]));
        }
        __syncthreads();
    }

    // Epilogue: out_raw[m] += sum_n relu(c + hb[b,n]) * Ws[n]
    #pragma unroll
    for (int mf = 0; mf < 4; mf++) {
        #pragma unroll
        for (int i = 0; i < 2; i++) {
            const int m = m0 + warp_m * 64 + mf * 16 + (lane >> 2) + i * 8;
            const int b = m & (B_SZ - 1);          // m = s*B + b
            float part = 0.0f;
            #pragma unroll
            for (int nf = 0; nf < 4; nf++) {
                #pragma unroll
                for (int j = 0; j < 2; j++) {
                    const int n = n0 + warp_n * 32 + nf * 8 + (lane & 3) * 2 + j;
                    const float v = c[mf][nf][i * 2 + j] + g_hb[b * H_DIM + n];
                    if (v > 0.0f) part += v * Ws[n];
                }
            }
            part += __shfl_xor_sync(0xffffffffu, part, 1);
            part += __shfl_xor_sync(0xffffffffu, part, 2);
            if ((lane & 3) == 0) atomicAdd(&g_attn_raw[m], part);
        }
    }
}

// ---------------- kernel 3: logits -> masked softmax over S per batch row ----------------
__global__ void softmax_kernel(const float* __restrict__ pe,
                               const void*  __restrict__ mask,
                               float* __restrict__ out,
                               float scale) {
    const int b   = blockIdx.x;
    const int tid = threadIdx.x;   // 256 threads, 2 s-values each
    __shared__ float red[256];
    const int mode = g_mask_mode;

    float v[2];
    #pragma unroll
    for (int q = 0; q < 2; q++) {
        const int s   = tid + q * 256;
        const int idx = b * S_LEN + s;
        float logit = scale * g_attn_raw[s * B_SZ + b] + pe[idx];
        bool msk;
        if      (mode == 1) msk = ((const unsigned char*)mask)[idx] != 0;
        else if (mode == 2) msk = ((const int*)mask)[idx] != 0;
        else if (mode == 3) msk = ((const float*)mask)[idx] != 0.0f;
        else                msk = false;
        v[q] = msk ? -1e12f : logit;
    }

    float mx = fmaxf(v[0], v[1]);
    red[tid] = mx;
    __syncthreads();
    #pragma unroll
    for (int o = 128; o; o >>= 1) {
        if (tid < o) red[tid] = fmaxf(red[tid], red[tid + o]);
        __syncthreads();
    }
    mx = red[0];
    __syncthreads();

    const float e0 = __expf(v[0] - mx);
    const float e1 = __expf(v[1] - mx);
    red[tid] = e0 + e1;
    __syncthreads();
    #pragma unroll
    for (int o = 128; o; o >>= 1) {
        if (tid < o) red[tid] += red[tid + o];
        __syncthreads();
    }
    const float inv = 1.0f / red[0];

    out[b * S_LEN + tid]       = e0 * inv;
    out[b * S_LEN + tid + 256] = e1 * inv;
}

// ---------------- launch ----------------
extern "C" void kernel_launch(void* const* d_in, const int* in_sizes, int n_in,
                              void* d_out, int out_size) {
    const float* hidden = (const float*)d_in[0];   // (1,B,H)
    const float* enc    = (const float*)d_in[1];   // (S,B,H)
    const float* pe     = (const float*)d_in[2];   // (B,S)
    const void*  mask   =               d_in[3];   // (B,S) bool-ish
    const float* Wa     = (const float*)d_in[4];   // (H,2H)
    const float* ba     = (const float*)d_in[5];   // (H)
    const float* Ws     = (const float*)d_in[6];   // (1,H)
    float* out = (float*)d_out;                    // (B,1,S)

    const float scale = (float)(log(512.0) / sqrt(1024.0));

    detect_and_zero<<<128, 256>>>((const unsigned char*)mask);
    convert_enc<<<4096, 256>>>(enc);
    convert_w<<<1024, 256>>>(Wa);
    hb_kernel<<<128, 256>>>(hidden, Wa, ba);
    gemm_kernel<<<dim3(NDIM / BN, M_TOT / BM), 256>>>(Ws);
    softmax_kernel<<<B_SZ, 256>>>(pe, mask, out, scale);
}

// round 7
// speedup vs baseline: 1.6006x; 1.6006x over previous
#include <cuda_runtime.h>
#include <cuda_fp16.h>
#include <math.h>
#include <stdint.h>

#define S_LEN 512
#define B_SZ  64
#define H_DIM 1024
#define M_TOT (S_LEN * B_SZ)
#define KDIM  H_DIM
#define NDIM  H_DIM

// ---------------- scratch ----------------
__device__ __half g_ench[M_TOT * H_DIM];   // enc fp16 [m][k]
__device__ __half g_Wh[H_DIM * H_DIM];     // Wa[:,H:2H] fp16 [n][k]
__device__ float  g_hb[B_SZ * H_DIM];      // hidden@Wa1^T + ba (fp32) [b][n]
__device__ float  g_attn_raw[M_TOT];
__device__ int    g_mask_mode;

// ---------------- kernel 0: zero scratch + detect mask dtype ----------------
__global__ void detect_and_zero(const unsigned char* __restrict__ mask_bytes) {
    for (int i = blockIdx.x * blockDim.x + threadIdx.x; i < M_TOT;
         i += gridDim.x * blockDim.x)
        g_attn_raw[i] = 0.0f;
    if (blockIdx.x == 0) {
        __shared__ int flag[4];
        if (threadIdx.x < 4) flag[threadIdx.x] = 0;
        __syncthreads();
        for (int i = threadIdx.x; i < B_SZ * S_LEN; i += blockDim.x)
            if (mask_bytes[i]) atomicOr(&flag[i & 3], 1);
        __syncthreads();
        if (threadIdx.x == 0) {
            int mode;
            if (flag[1])                mode = 1;
            else if (flag[0])           mode = 2;
            else if (flag[2] | flag[3]) mode = 3;
            else                        mode = 0;
            g_mask_mode = mode;
        }
    }
}

// ---------------- converters ----------------
__global__ void convert_enc(const float* __restrict__ enc) {
    const int n4 = M_TOT * H_DIM / 4;
    for (int i = blockIdx.x * blockDim.x + threadIdx.x; i < n4;
         i += gridDim.x * blockDim.x) {
        float4 v = ((const float4*)enc)[i];
        __half2* dst = (__half2*)g_ench;
        dst[2 * i]     = __floats2half2_rn(v.x, v.y);
        dst[2 * i + 1] = __floats2half2_rn(v.z, v.w);
    }
}
__global__ void convert_w(const float* __restrict__ Wa) {
    const int n4 = H_DIM * H_DIM / 4;
    for (int i = blockIdx.x * blockDim.x + threadIdx.x; i < n4;
         i += gridDim.x * blockDim.x) {
        const int n  = i >> 8;
        const int kc = i & 255;
        float4 v = *(const float4*)(Wa + (size_t)n * (2 * H_DIM) + H_DIM + kc * 4);
        __half2* dst = (__half2*)(g_Wh + (size_t)n * H_DIM + kc * 4);
        dst[0] = __floats2half2_rn(v.x, v.y);
        dst[1] = __floats2half2_rn(v.z, v.w);
    }
}

// ---------------- hb: g_hb[b][n] = hidden[b,:].Wa[n,0:H] + ba[n] ----------------
// 64 blocks x 256 thr; block = 16 n-cols, all 64 b. K tiled by 128 via smem.
__global__ __launch_bounds__(256) void hb_kernel(const float* __restrict__ hidden,
                                                 const float* __restrict__ Wa,
                                                 const float* __restrict__ ba) {
    __shared__ float hid_s[B_SZ][128];   // 32KB
    const int tid   = threadIdx.x;
    const int n_loc = tid & 15;
    const int bg    = tid >> 4;          // 0..15 -> group of 4 b values
    const int n     = blockIdx.x * 16 + n_loc;
    const float* wrow = Wa + (size_t)n * (2 * H_DIM);
    float acc[4] = {0.f, 0.f, 0.f, 0.f};

    for (int k0 = 0; k0 < H_DIM; k0 += 128) {
        __syncthreads();
        #pragma unroll
        for (int i = 0; i < 8; i++) {
            int lin = i * 256 + tid;     // 2048 float4
            int b = lin >> 5, c = lin & 31;
            *(float4*)(&hid_s[b][c * 4]) = *(const float4*)(hidden + b * H_DIM + k0 + c * 4);
        }
        __syncthreads();
        #pragma unroll 8
        for (int kk = 0; kk < 128; kk += 4) {
            float4 w = *(const float4*)(wrow + k0 + kk);
            #pragma unroll
            for (int j = 0; j < 4; j++) {
                float4 h = *(const float4*)(&hid_s[bg * 4 + j][kk]);
                acc[j] += w.x * h.x + w.y * h.y + w.z * h.z + w.w * h.w;
            }
        }
    }
    const float bias = ba[n];
    #pragma unroll
    for (int j = 0; j < 4; j++)
        g_hb[(bg * 4 + j) * H_DIM + n] = acc[j] + bias;
}

// ---------------- fused GEMM: fp16 mma.sync + ldmatrix + cp.async pipeline ----------------
#define BM 128
#define BN 128
#define BK 64
#define AST 72                       // halfs per smem row (64 + 8 pad); 144B, 16B-aligned
#define NT (KDIM / BK)               // 16
#define STAGE_HALFS ((BM + BN) * AST)   // A then B
#define STAGE_BYTES (STAGE_HALFS * 2)   // 36864
#define GSMEM (2 * STAGE_BYTES)         // 73728

__global__ __launch_bounds__(256, 2)
void gemm_kernel(const float* __restrict__ Ws) {
    extern __shared__ __half sm[];

    const int tid    = threadIdx.x;
    const int warp   = tid >> 5;
    const int lane   = tid & 31;
    const int warp_m = warp >> 2;   // 0..1
    const int warp_n = warp & 3;    // 0..3
    const int n0 = blockIdx.x * BN;
    const int m0 = blockIdx.y * BM;

    float c[4][4][4];
    #pragma unroll
    for (int a = 0; a < 4; a++)
        #pragma unroll
        for (int b = 0; b < 4; b++)
            #pragma unroll
            for (int d = 0; d < 4; d++) c[a][b][d] = 0.0f;

    // ---- async loaders: per stage 2048 x 16B chunks (A 1024, B 1024), 8/thread ----
    const uint32_t s_base = (uint32_t)__cvta_generic_to_shared(sm);

    #define ISSUE_STAGE(st, k0)                                                     \
        do {                                                                        \
            _Pragma("unroll")                                                       \
            for (int i = 0; i < 8; i++) {                                           \
                const int lin = i * 256 + tid;                                      \
                const int isB = lin >> 10;                                          \
                const int l   = lin & 1023;                                         \
                const int row = l >> 3, cc = l & 7;                                 \
                const __half* src = (isB ? g_Wh + (size_t)(n0 + row) * KDIM         \
                                         : g_ench + (size_t)(m0 + row) * KDIM)      \
                                    + (k0) + cc * 8;                                \
                const uint32_t dst = s_base + (st) * STAGE_BYTES                    \
                                   + (isB * BM + row) * (AST * 2) + cc * 16;        \
                asm volatile("cp.async.cg.shared.global [%0], [%1], 16;\n"          \
                             :: "r"(dst), "l"(src));                                \
            }                                                                       \
            asm volatile("cp.async.commit_group;\n");                               \
        } while (0)

    ISSUE_STAGE(0, 0);

    // ldmatrix source addresses (fixed per thread, per stage offset added in loop)
    // A (x4): m0 rows0-7 col kk | m1 rows8-15 col kk | m2 rows0-7 kk+8 | m3 rows8-15 kk+8
    const int a_row = warp_m * 64 + (lane & 7) + ((lane >> 3) & 1) * 8;  // + mf*16
    const int a_col = ((lane >> 4) & 1) * 8;                              // + kk
    // B (x4): covers nf pair (2g,2g+1):
    const int b_row = warp_n * 32 + ((lane >> 4) & 1) * 8 + (lane & 7);   // + g*16
    const int b_col = ((lane >> 3) & 1) * 8;                              // + kk

    for (int kt = 0; kt < NT; kt++) {
        const int cur = kt & 1;
        if (kt + 1 < NT) {
            ISSUE_STAGE((kt + 1) & 1, (kt + 1) * BK);
            asm volatile("cp.async.wait_group 1;\n" ::: "memory");
        } else {
            asm volatile("cp.async.wait_group 0;\n" ::: "memory");
        }
        __syncthreads();

        const uint32_t sA = s_base + cur * STAGE_BYTES;
        const uint32_t sB = sA + BM * (AST * 2);

        #pragma unroll
        for (int kk = 0; kk < BK; kk += 16) {
            uint32_t af[4][4], bf[2][4];
            #pragma unroll
            for (int mf = 0; mf < 4; mf++) {
                const uint32_t addr = sA + (a_row + mf * 16) * (AST * 2)
                                         + (a_col + kk) * 2;
                asm volatile("ldmatrix.sync.aligned.m8n8.x4.shared.b16 "
                             "{%0,%1,%2,%3}, [%4];"
                             : "=r"(af[mf][0]), "=r"(af[mf][1]),
                               "=r"(af[mf][2]), "=r"(af[mf][3]) : "r"(addr));
            }
            #pragma unroll
            for (int g = 0; g < 2; g++) {
                const uint32_t addr = sB + (b_row + g * 16) * (AST * 2)
                                         + (b_col + kk) * 2;
                asm volatile("ldmatrix.sync.aligned.m8n8.x4.shared.b16 "
                             "{%0,%1,%2,%3}, [%4];"
                             : "=r"(bf[g][0]), "=r"(bf[g][1]),
                               "=r"(bf[g][2]), "=r"(bf[g][3]) : "r"(addr));
            }
            #pragma unroll
            for (int mf = 0; mf < 4; mf++)
                #pragma unroll
                for (int nf = 0; nf < 4; nf++)
                    asm volatile(
                        "mma.sync.aligned.m16n8k16.row.col.f32.f16.f16.f32 "
                        "{%0,%1,%2,%3}, {%4,%5,%6,%7}, {%8,%9}, {%0,%1,%2,%3};\n"
                        : "+f"(c[mf][nf][0]), "+f"(c[mf][nf][1]),
                          "+f"(c[mf][nf][2]), "+f"(c[mf][nf][3])
                        : "r"(af[mf][0]), "r"(af[mf][1]),
                          "r"(af[mf][2]), "r"(af[mf][3]),
                          "r"(bf[nf >> 1][(nf & 1) * 2]),
                          "r"(bf[nf >> 1][(nf & 1) * 2 + 1]));
        }
        __syncthreads();
    }

    // Epilogue: out_raw[m] += sum_n relu(c + hb[b,n]) * Ws[n]
    #pragma unroll
    for (int mf = 0; mf < 4; mf++) {
        #pragma unroll
        for (int i = 0; i < 2; i++) {
            const int m = m0 + warp_m * 64 + mf * 16 + (lane >> 2) + i * 8;
            const int b = m & (B_SZ - 1);          // m = s*B + b
            float part = 0.0f;
            #pragma unroll
            for (int nf = 0; nf < 4; nf++) {
                #pragma unroll
                for (int j = 0; j < 2; j++) {
                    const int n = n0 + warp_n * 32 + nf * 8 + (lane & 3) * 2 + j;
                    const float v = c[mf][nf][i * 2 + j] + g_hb[b * H_DIM + n];
                    if (v > 0.0f) part += v * Ws[n];
                }
            }
            part += __shfl_xor_sync(0xffffffffu, part, 1);
            part += __shfl_xor_sync(0xffffffffu, part, 2);
            if ((lane & 3) == 0) atomicAdd(&g_attn_raw[m], part);
        }
    }
}

// ---------------- softmax ----------------
__global__ void softmax_kernel(const float* __restrict__ pe,
                               const void*  __restrict__ mask,
                               float* __restrict__ out, float scale) {
    const int b   = blockIdx.x;
    const int tid = threadIdx.x;
    __shared__ float red[256];
    const int mode = g_mask_mode;

    float v[2];
    #pragma unroll
    for (int q = 0; q < 2; q++) {
        const int s   = tid + q * 256;
        const int idx = b * S_LEN + s;
        float logit = scale * g_attn_raw[s * B_SZ + b] + pe[idx];
        bool msk;
        if      (mode == 1) msk = ((const unsigned char*)mask)[idx] != 0;
        else if (mode == 2) msk = ((const int*)mask)[idx] != 0;
        else if (mode == 3) msk = ((const float*)mask)[idx] != 0.0f;
        else                msk = false;
        v[q] = msk ? -1e12f : logit;
    }
    float mx = fmaxf(v[0], v[1]);
    red[tid] = mx; __syncthreads();
    #pragma unroll
    for (int o = 128; o; o >>= 1) {
        if (tid < o) red[tid] = fmaxf(red[tid], red[tid + o]);
        __syncthreads();
    }
    mx = red[0]; __syncthreads();
    const float e0 = __expf(v[0] - mx);
    const float e1 = __expf(v[1] - mx);
    red[tid] = e0 + e1; __syncthreads();
    #pragma unroll
    for (int o = 128; o; o >>= 1) {
        if (tid < o) red[tid] += red[tid + o];
        __syncthreads();
    }
    const float inv = 1.0f / red[0];
    out[b * S_LEN + tid]       = e0 * inv;
    out[b * S_LEN + tid + 256] = e1 * inv;
}

// ---------------- launch ----------------
extern "C" void kernel_launch(void* const* d_in, const int* in_sizes, int n_in,
                              void* d_out, int out_size) {
    const float* hidden = (const float*)d_in[0];
    const float* enc    = (const float*)d_in[1];
    const float* pe     = (const float*)d_in[2];
    const void*  mask   =               d_in[3];
    const float* Wa     = (const float*)d_in[4];
    const float* ba     = (const float*)d_in[5];
    const float* Ws     = (const float*)d_in[6];
    float* out = (float*)d_out;

    const float scale = (float)(log(512.0) / sqrt(1024.0));

    static int smem_set = 0;
    if (!smem_set) {
        cudaFuncSetAttribute(gemm_kernel, cudaFuncAttributeMaxDynamicSharedMemorySize, GSMEM);
        smem_set = 1;
    }

    detect_and_zero<<<128, 256>>>((const unsigned char*)mask);
    convert_enc<<<4096, 256>>>(enc);
    convert_w<<<1024, 256>>>(Wa);
    hb_kernel<<<64, 256>>>(hidden, Wa, ba);
    gemm_kernel<<<dim3(NDIM / BN, M_TOT / BM), 256, GSMEM>>>(Ws);
    softmax_kernel<<<B_SZ, 256>>>(pe, mask, out, scale);
}

// round 8
// speedup vs baseline: 1.8920x; 1.1820x over previous
#include <cuda_runtime.h>
#include <cuda_fp16.h>
#include <math.h>
#include <stdint.h>

#define S_LEN 512
#define B_SZ  64
#define H_DIM 1024
#define M_TOT (S_LEN * B_SZ)
#define KDIM  H_DIM
#define NDIM  H_DIM

// ---------------- scratch ----------------
__device__ __half g_ench[M_TOT * H_DIM];   // enc fp16 [m][k]
__device__ __half g_Wh[H_DIM * H_DIM];     // Wa[:,H:2H] fp16 [n][k]
__device__ float  g_hb[B_SZ * H_DIM];      // hidden@Wa1^T + ba (fp32) [b][n]
__device__ float  g_attn_raw[M_TOT];
__device__ int    g_mask_mode;

// ---------------- kernel 0: zero attn_raw, seed g_hb with bias, detect mask dtype ----------------
__global__ void detect_and_zero(const unsigned char* __restrict__ mask_bytes,
                                const float* __restrict__ ba) {
    const int gstride = gridDim.x * blockDim.x;
    for (int i = blockIdx.x * blockDim.x + threadIdx.x; i < M_TOT; i += gstride)
        g_attn_raw[i] = 0.0f;
    for (int i = blockIdx.x * blockDim.x + threadIdx.x; i < B_SZ * H_DIM; i += gstride)
        g_hb[i] = ba[i & (H_DIM - 1)];

    if (blockIdx.x == 0) {
        __shared__ int flag[4];
        if (threadIdx.x < 4) flag[threadIdx.x] = 0;
        __syncthreads();
        for (int i = threadIdx.x; i < B_SZ * S_LEN; i += blockDim.x)
            if (mask_bytes[i]) atomicOr(&flag[i & 3], 1);
        __syncthreads();
        if (threadIdx.x == 0) {
            int mode;
            if (flag[1])                mode = 1;
            else if (flag[0])           mode = 2;
            else if (flag[2] | flag[3]) mode = 3;
            else                        mode = 0;
            g_mask_mode = mode;
        }
    }
}

// ---------------- converters ----------------
__global__ void convert_enc(const float* __restrict__ enc) {
    const int n4 = M_TOT * H_DIM / 4;
    for (int i = blockIdx.x * blockDim.x + threadIdx.x; i < n4;
         i += gridDim.x * blockDim.x) {
        float4 v = ((const float4*)enc)[i];
        __half2* dst = (__half2*)g_ench;
        dst[2 * i]     = __floats2half2_rn(v.x, v.y);
        dst[2 * i + 1] = __floats2half2_rn(v.z, v.w);
    }
}
__global__ void convert_w(const float* __restrict__ Wa) {
    const int n4 = H_DIM * H_DIM / 4;
    for (int i = blockIdx.x * blockDim.x + threadIdx.x; i < n4;
         i += gridDim.x * blockDim.x) {
        const int n  = i >> 8;
        const int kc = i & 255;
        float4 v = *(const float4*)(Wa + (size_t)n * (2 * H_DIM) + H_DIM + kc * 4);
        __half2* dst = (__half2*)(g_Wh + (size_t)n * H_DIM + kc * 4);
        dst[0] = __floats2half2_rn(v.x, v.y);
        dst[1] = __floats2half2_rn(v.z, v.w);
    }
}

// ---------------- hb: g_hb[b][n] += hidden[b, ks].Wa[n, ks]  (k-split x 8) ----------------
// grid (64 n-tiles, 8 k-slices) x 256 thr. Block: 16 n x 64 b x 128 k.
__global__ __launch_bounds__(256) void hb_kernel(const float* __restrict__ hidden,
                                                 const float* __restrict__ Wa) {
    __shared__ float hid_s[B_SZ][128];   // 32KB slice of hidden
    const int tid   = threadIdx.x;
    const int n_loc = tid & 15;
    const int bg    = tid >> 4;          // 0..15 -> group of 4 b values
    const int n     = blockIdx.x * 16 + n_loc;
    const int k0    = blockIdx.y * 128;

    #pragma unroll
    for (int i = 0; i < 8; i++) {
        int lin = i * 256 + tid;         // 2048 float4
        int b = lin >> 5, c = lin & 31;
        *(float4*)(&hid_s[b][c * 4]) = *(const float4*)(hidden + b * H_DIM + k0 + c * 4);
    }
    __syncthreads();

    const float* wrow = Wa + (size_t)n * (2 * H_DIM) + k0;
    float acc[4] = {0.f, 0.f, 0.f, 0.f};
    #pragma unroll 8
    for (int kk = 0; kk < 128; kk += 4) {
        float4 w = *(const float4*)(wrow + kk);
        #pragma unroll
        for (int j = 0; j < 4; j++) {
            float4 h = *(const float4*)(&hid_s[bg * 4 + j][kk]);
            acc[j] += w.x * h.x + w.y * h.y + w.z * h.z + w.w * h.w;
        }
    }
    #pragma unroll
    for (int j = 0; j < 4; j++)
        atomicAdd(&g_hb[(bg * 4 + j) * H_DIM + n], acc[j]);
}

// ---------------- fused GEMM: fp16 mma.sync + ldmatrix + cp.async pipeline ----------------
#define BM 128
#define BN 128
#define BK 64
#define AST 72                       // halfs per smem row (64 + 8 pad); 144B, 16B-aligned
#define NT (KDIM / BK)               // 16
#define STAGE_HALFS ((BM + BN) * AST)   // A then B
#define STAGE_BYTES (STAGE_HALFS * 2)   // 36864
#define GSMEM (2 * STAGE_BYTES)         // 73728

__global__ __launch_bounds__(256, 2)
void gemm_kernel(const float* __restrict__ Ws) {
    extern __shared__ __half sm[];

    const int tid    = threadIdx.x;
    const int warp   = tid >> 5;
    const int lane   = tid & 31;
    const int warp_m = warp >> 2;   // 0..1
    const int warp_n = warp & 3;    // 0..3
    const int n0 = blockIdx.x * BN;
    const int m0 = blockIdx.y * BM;

    float c[4][4][4];
    #pragma unroll
    for (int a = 0; a < 4; a++)
        #pragma unroll
        for (int b = 0; b < 4; b++)
            #pragma unroll
            for (int d = 0; d < 4; d++) c[a][b][d] = 0.0f;

    const uint32_t s_base = (uint32_t)__cvta_generic_to_shared(sm);

    #define ISSUE_STAGE(st, k0)                                                     \
        do {                                                                        \
            _Pragma("unroll")                                                       \
            for (int i = 0; i < 8; i++) {                                           \
                const int lin = i * 256 + tid;                                      \
                const int isB = lin >> 10;                                          \
                const int l   = lin & 1023;                                         \
                const int row = l >> 3, cc = l & 7;                                 \
                const __half* src = (isB ? g_Wh + (size_t)(n0 + row) * KDIM         \
                                         : g_ench + (size_t)(m0 + row) * KDIM)      \
                                    + (k0) + cc * 8;                                \
                const uint32_t dst = s_base + (st) * STAGE_BYTES                    \
                                   + (isB * BM + row) * (AST * 2) + cc * 16;        \
                asm volatile("cp.async.cg.shared.global [%0], [%1], 16;\n"          \
                             :: "r"(dst), "l"(src));                                \
            }                                                                       \
            asm volatile("cp.async.commit_group;\n");                               \
        } while (0)

    ISSUE_STAGE(0, 0);

    const int a_row = warp_m * 64 + (lane & 7) + ((lane >> 3) & 1) * 8;  // + mf*16
    const int a_col = ((lane >> 4) & 1) * 8;                              // + kk
    const int b_row = warp_n * 32 + ((lane >> 4) & 1) * 8 + (lane & 7);   // + g*16
    const int b_col = ((lane >> 3) & 1) * 8;                              // + kk

    for (int kt = 0; kt < NT; kt++) {
        const int cur = kt & 1;
        if (kt + 1 < NT) {
            ISSUE_STAGE((kt + 1) & 1, (kt + 1) * BK);
            asm volatile("cp.async.wait_group 1;\n" ::: "memory");
        } else {
            asm volatile("cp.async.wait_group 0;\n" ::: "memory");
        }
        __syncthreads();

        const uint32_t sA = s_base + cur * STAGE_BYTES;
        const uint32_t sB = sA + BM * (AST * 2);

        #pragma unroll
        for (int kk = 0; kk < BK; kk += 16) {
            uint32_t af[4][4], bf[2][4];
            #pragma unroll
            for (int mf = 0; mf < 4; mf++) {
                const uint32_t addr = sA + (a_row + mf * 16) * (AST * 2)
                                         + (a_col + kk) * 2;
                asm volatile("ldmatrix.sync.aligned.m8n8.x4.shared.b16 "
                             "{%0,%1,%2,%3}, [%4];"
                             : "=r"(af[mf][0]), "=r"(af[mf][1]),
                               "=r"(af[mf][2]), "=r"(af[mf][3]) : "r"(addr));
            }
            #pragma unroll
            for (int g = 0; g < 2; g++) {
                const uint32_t addr = sB + (b_row + g * 16) * (AST * 2)
                                         + (b_col + kk) * 2;
                asm volatile("ldmatrix.sync.aligned.m8n8.x4.shared.b16 "
                             "{%0,%1,%2,%3}, [%4];"
                             : "=r"(bf[g][0]), "=r"(bf[g][1]),
                               "=r"(bf[g][2]), "=r"(bf[g][3]) : "r"(addr));
            }
            #pragma unroll
            for (int mf = 0; mf < 4; mf++)
                #pragma unroll
                for (int nf = 0; nf < 4; nf++)
                    asm volatile(
                        "mma.sync.aligned.m16n8k16.row.col.f32.f16.f16.f32 "
                        "{%0,%1,%2,%3}, {%4,%5,%6,%7}, {%8,%9}, {%0,%1,%2,%3};\n"
                        : "+f"(c[mf][nf][0]), "+f"(c[mf][nf][1]),
                          "+f"(c[mf][nf][2]), "+f"(c[mf][nf][3])
                        : "r"(af[mf][0]), "r"(af[mf][1]),
                          "r"(af[mf][2]), "r"(af[mf][3]),
                          "r"(bf[nf >> 1][(nf & 1) * 2]),
                          "r"(bf[nf >> 1][(nf & 1) * 2 + 1]));
        }
        __syncthreads();
    }

    // Epilogue: out_raw[m] += sum_n relu(c + hb[b,n]) * Ws[n]
    #pragma unroll
    for (int mf = 0; mf < 4; mf++) {
        #pragma unroll
        for (int i = 0; i < 2; i++) {
            const int m = m0 + warp_m * 64 + mf * 16 + (lane >> 2) + i * 8;
            const int b = m & (B_SZ - 1);          // m = s*B + b
            float part = 0.0f;
            #pragma unroll
            for (int nf = 0; nf < 4; nf++) {
                #pragma unroll
                for (int j = 0; j < 2; j++) {
                    const int n = n0 + warp_n * 32 + nf * 8 + (lane & 3) * 2 + j;
                    const float v = c[mf][nf][i * 2 + j] + g_hb[b * H_DIM + n];
                    if (v > 0.0f) part += v * Ws[n];
                }
            }
            part += __shfl_xor_sync(0xffffffffu, part, 1);
            part += __shfl_xor_sync(0xffffffffu, part, 2);
            if ((lane & 3) == 0) atomicAdd(&g_attn_raw[m], part);
        }
    }
}

// ---------------- softmax ----------------
__global__ void softmax_kernel(const float* __restrict__ pe,
                               const void*  __restrict__ mask,
                               float* __restrict__ out, float scale) {
    const int b   = blockIdx.x;
    const int tid = threadIdx.x;
    __shared__ float red[256];
    const int mode = g_mask_mode;

    float v[2];
    #pragma unroll
    for (int q = 0; q < 2; q++) {
        const int s   = tid + q * 256;
        const int idx = b * S_LEN + s;
        float logit = scale * g_attn_raw[s * B_SZ + b] + pe[idx];
        bool msk;
        if      (mode == 1) msk = ((const unsigned char*)mask)[idx] != 0;
        else if (mode == 2) msk = ((const int*)mask)[idx] != 0;
        else if (mode == 3) msk = ((const float*)mask)[idx] != 0.0f;
        else                msk = false;
        v[q] = msk ? -1e12f : logit;
    }
    float mx = fmaxf(v[0], v[1]);
    red[tid] = mx; __syncthreads();
    #pragma unroll
    for (int o = 128; o; o >>= 1) {
        if (tid < o) red[tid] = fmaxf(red[tid], red[tid + o]);
        __syncthreads();
    }
    mx = red[0]; __syncthreads();
    const float e0 = __expf(v[0] - mx);
    const float e1 = __expf(v[1] - mx);
    red[tid] = e0 + e1; __syncthreads();
    #pragma unroll
    for (int o = 128; o; o >>= 1) {
        if (tid < o) red[tid] += red[tid + o];
        __syncthreads();
    }
    const float inv = 1.0f / red[0];
    out[b * S_LEN + tid]       = e0 * inv;
    out[b * S_LEN + tid + 256] = e1 * inv;
}

// ---------------- launch ----------------
extern "C" void kernel_launch(void* const* d_in, const int* in_sizes, int n_in,
                              void* d_out, int out_size) {
    const float* hidden = (const float*)d_in[0];
    const float* enc    = (const float*)d_in[1];
    const float* pe     = (const float*)d_in[2];
    const void*  mask   =               d_in[3];
    const float* Wa     = (const float*)d_in[4];
    const float* ba     = (const float*)d_in[5];
    const float* Ws     = (const float*)d_in[6];
    float* out = (float*)d_out;

    const float scale = (float)(log(512.0) / sqrt(1024.0));

    static int smem_set = 0;
    if (!smem_set) {
        cudaFuncSetAttribute(gemm_kernel, cudaFuncAttributeMaxDynamicSharedMemorySize, GSMEM);
        smem_set = 1;
    }

    detect_and_zero<<<128, 256>>>((const unsigned char*)mask, ba);
    convert_enc<<<4096, 256>>>(enc);
    convert_w<<<1024, 256>>>(Wa);
    hb_kernel<<<dim3(64, 8), 256>>>(hidden, Wa);
    gemm_kernel<<<dim3(NDIM / BN, M_TOT / BM), 256, GSMEM>>>(Ws);
    softmax_kernel<<<B_SZ, 256>>>(pe, mask, out, scale);
}

// round 9
// speedup vs baseline: 2.1218x; 1.1215x over previous
#include <cuda_runtime.h>
#include <cuda_fp16.h>
#include <math.h>
#include <stdint.h>

#define S_LEN 512
#define B_SZ  64
#define H_DIM 1024
#define M_TOT (S_LEN * B_SZ)
#define KDIM  H_DIM
#define NDIM  H_DIM

// ---------------- scratch ----------------
__device__ __half g_ench[M_TOT * H_DIM];   // enc fp16 [m][k]
__device__ __half g_Wh[H_DIM * H_DIM];     // Wa[:,H:2H] fp16 [n][k]
__device__ float  g_hb[B_SZ * H_DIM];      // hidden@Wa1^T + ba (fp32) [b][n]
__device__ float  g_attn_raw[M_TOT];
__device__ int    g_mask_mode;

// ---------------- kernel 0: zero attn_raw, seed g_hb, detect mask dtype, convert W ----------------
__global__ void init_kernel(const unsigned char* __restrict__ mask_bytes,
                            const float* __restrict__ ba,
                            const float* __restrict__ Wa) {
    const int gstride = gridDim.x * blockDim.x;
    const int gtid = blockIdx.x * blockDim.x + threadIdx.x;
    for (int i = gtid; i < M_TOT; i += gstride)
        g_attn_raw[i] = 0.0f;
    for (int i = gtid; i < B_SZ * H_DIM; i += gstride)
        g_hb[i] = ba[i & (H_DIM - 1)];
    // convert Wa[:, H:2H] -> fp16 [n][k]
    const int n4 = H_DIM * H_DIM / 4;
    for (int i = gtid; i < n4; i += gstride) {
        const int n  = i >> 8;
        const int kc = i & 255;
        float4 v = *(const float4*)(Wa + (size_t)n * (2 * H_DIM) + H_DIM + kc * 4);
        __half2* dst = (__half2*)(g_Wh + (size_t)n * H_DIM + kc * 4);
        dst[0] = __floats2half2_rn(v.x, v.y);
        dst[1] = __floats2half2_rn(v.z, v.w);
    }
    if (blockIdx.x == 0) {
        __shared__ int flag[4];
        if (threadIdx.x < 4) flag[threadIdx.x] = 0;
        __syncthreads();
        for (int i = threadIdx.x; i < B_SZ * S_LEN; i += blockDim.x)
            if (mask_bytes[i]) atomicOr(&flag[i & 3], 1);
        __syncthreads();
        if (threadIdx.x == 0) {
            int mode;
            if (flag[1])                mode = 1;
            else if (flag[0])           mode = 2;
            else if (flag[2] | flag[3]) mode = 3;
            else                        mode = 0;
            g_mask_mode = mode;
        }
    }
}

// ---------------- convert enc -> fp16 ----------------
__global__ void convert_enc(const float* __restrict__ enc) {
    const int n4 = M_TOT * H_DIM / 4;
    for (int i = blockIdx.x * blockDim.x + threadIdx.x; i < n4;
         i += gridDim.x * blockDim.x) {
        float4 v = ((const float4*)enc)[i];
        __half2* dst = (__half2*)g_ench;
        dst[2 * i]     = __floats2half2_rn(v.x, v.y);
        dst[2 * i + 1] = __floats2half2_rn(v.z, v.w);
    }
}

// ---------------- hb: g_hb[b][n] += hidden[b, ks].Wa[n, ks]  (k-split x 8) ----------------
__global__ __launch_bounds__(256) void hb_kernel(const float* __restrict__ hidden,
                                                 const float* __restrict__ Wa) {
    __shared__ float hid_s[B_SZ][132];   // 132-stride: breaks bg-group bank conflicts
    const int tid   = threadIdx.x;
    const int n_loc = tid & 15;
    const int bg    = tid >> 4;          // 0..15 -> group of 4 b values
    const int n     = blockIdx.x * 16 + n_loc;
    const int k0    = blockIdx.y * 128;

    #pragma unroll
    for (int i = 0; i < 8; i++) {
        int lin = i * 256 + tid;         // 2048 float4
        int b = lin >> 5, c = lin & 31;
        *(float4*)(&hid_s[b][c * 4]) = *(const float4*)(hidden + b * H_DIM + k0 + c * 4);
    }
    __syncthreads();

    const float* wrow = Wa + (size_t)n * (2 * H_DIM) + k0;
    float acc[4] = {0.f, 0.f, 0.f, 0.f};
    #pragma unroll 8
    for (int kk = 0; kk < 128; kk += 4) {
        float4 w = *(const float4*)(wrow + kk);
        #pragma unroll
        for (int j = 0; j < 4; j++) {
            float4 h = *(const float4*)(&hid_s[bg * 4 + j][kk]);
            acc[j] += w.x * h.x + w.y * h.y + w.z * h.z + w.w * h.w;
        }
    }
    #pragma unroll
    for (int j = 0; j < 4; j++)
        atomicAdd(&g_hb[(bg * 4 + j) * H_DIM + n], acc[j]);
}

// ---------------- fused GEMM: fp16 mma.sync + ldmatrix + 3-stage cp.async, SW128 smem ----------------
#define BM 128
#define BN 128
#define BK 64
#define NT (KDIM / BK)               // 16
#define STAGE_BYTES 32768            // A 128x128B + B 128x128B
#define NSTAGE 3
#define GSMEM (NSTAGE * STAGE_BYTES) // 98304

__global__ __launch_bounds__(256, 2)
void gemm_kernel(const float* __restrict__ Ws) {
    extern __shared__ __half sm[];

    const int tid    = threadIdx.x;
    const int warp   = tid >> 5;
    const int lane   = tid & 31;
    const int warp_m = warp >> 2;   // 0..1
    const int warp_n = warp & 3;    // 0..3
    const int n0 = blockIdx.x * BN;
    const int m0 = blockIdx.y * BM;

    float c[4][4][4];
    #pragma unroll
    for (int a = 0; a < 4; a++)
        #pragma unroll
        for (int b = 0; b < 4; b++)
            #pragma unroll
            for (int d = 0; d < 4; d++) c[a][b][d] = 0.0f;

    const uint32_t s_base = (uint32_t)__cvta_generic_to_shared(sm);

    // per stage: 2048 16B chunks (A 128rows x 8chunks, B same), 8 per thread, SW128 swizzle
    #define ISSUE_STAGE(st, k0)                                                     \
        do {                                                                        \
            _Pragma("unroll")                                                       \
            for (int i = 0; i < 8; i++) {                                           \
                const int lin = i * 256 + tid;                                      \
                const int isB = lin >> 10;                                          \
                const int l   = lin & 1023;                                         \
                const int row = l >> 3, cc = l & 7;                                 \
                const __half* src = (isB ? g_Wh + (size_t)(n0 + row) * KDIM         \
                                         : g_ench + (size_t)(m0 + row) * KDIM)      \
                                    + (k0) + cc * 8;                                \
                const uint32_t dst = s_base + (st) * STAGE_BYTES + isB * 16384      \
                                   + row * 128 + ((cc ^ (row & 7)) << 4);           \
                asm volatile("cp.async.cg.shared.global [%0], [%1], 16;\n"          \
                             :: "r"(dst), "l"(src));                                \
            }                                                                       \
            asm volatile("cp.async.commit_group;\n");                               \
        } while (0)

    ISSUE_STAGE(0, 0);
    ISSUE_STAGE(1, BK);

    // ldmatrix fragment rows/chunk bases (per thread)
    const int a_row  = warp_m * 64 + (lane & 7) + ((lane >> 3) & 1) * 8;  // + mf*16
    const int a_chk  = (lane >> 4) & 1;                                    // + kk>>3
    const int b_rowb = warp_n * 32 + ((lane >> 4) & 1) * 8 + (lane & 7);   // + g*16
    const int b_chk  = (lane >> 3) & 1;                                    // + kk>>3

    for (int kt = 0; kt < NT; kt++) {
        const int cur = kt % NSTAGE;
        if (kt + 2 < NT) ISSUE_STAGE((kt + 2) % NSTAGE, (kt + 2) * BK);

        if (kt < NT - 2)       asm volatile("cp.async.wait_group 2;\n" ::: "memory");
        else if (kt == NT - 2) asm volatile("cp.async.wait_group 1;\n" ::: "memory");
        else                   asm volatile("cp.async.wait_group 0;\n" ::: "memory");
        __syncthreads();

        const uint32_t sA = s_base + cur * STAGE_BYTES;
        const uint32_t sB = sA + 16384;

        #pragma unroll
        for (int kk = 0; kk < BK; kk += 16) {
            uint32_t af[4][4], bf[2][4];
            #pragma unroll
            for (int mf = 0; mf < 4; mf++) {
                const int row = a_row + mf * 16;
                const int chk = a_chk + (kk >> 3);
                const uint32_t addr = sA + row * 128 + ((chk ^ (row & 7)) << 4);
                asm volatile("ldmatrix.sync.aligned.m8n8.x4.shared.b16 "
                             "{%0,%1,%2,%3}, [%4];"
                             : "=r"(af[mf][0]), "=r"(af[mf][1]),
                               "=r"(af[mf][2]), "=r"(af[mf][3]) : "r"(addr));
            }
            #pragma unroll
            for (int g = 0; g < 2; g++) {
                const int row = b_rowb + g * 16;
                const int chk = b_chk + (kk >> 3);
                const uint32_t addr = sB + row * 128 + ((chk ^ (row & 7)) << 4);
                asm volatile("ldmatrix.sync.aligned.m8n8.x4.shared.b16 "
                             "{%0,%1,%2,%3}, [%4];"
                             : "=r"(bf[g][0]), "=r"(bf[g][1]),
                               "=r"(bf[g][2]), "=r"(bf[g][3]) : "r"(addr));
            }
            #pragma unroll
            for (int mf = 0; mf < 4; mf++)
                #pragma unroll
                for (int nf = 0; nf < 4; nf++)
                    asm volatile(
                        "mma.sync.aligned.m16n8k16.row.col.f32.f16.f16.f32 "
                        "{%0,%1,%2,%3}, {%4,%5,%6,%7}, {%8,%9}, {%0,%1,%2,%3};\n"
                        : "+f"(c[mf][nf][0]), "+f"(c[mf][nf][1]),
                          "+f"(c[mf][nf][2]), "+f"(c[mf][nf][3])
                        : "r"(af[mf][0]), "r"(af[mf][1]),
                          "r"(af[mf][2]), "r"(af[mf][3]),
                          "r"(bf[nf >> 1][(nf & 1) * 2]),
                          "r"(bf[nf >> 1][(nf & 1) * 2 + 1]));
        }
        __syncthreads();
    }

    // Epilogue: out_raw[m] += sum_n relu(c + hb[b,n]) * Ws[n]
    #pragma unroll
    for (int mf = 0; mf < 4; mf++) {
        #pragma unroll
        for (int i = 0; i < 2; i++) {
            const int m = m0 + warp_m * 64 + mf * 16 + (lane >> 2) + i * 8;
            const int b = m & (B_SZ - 1);          // m = s*B + b
            float part = 0.0f;
            #pragma unroll
            for (int nf = 0; nf < 4; nf++) {
                #pragma unroll
                for (int j = 0; j < 2; j++) {
                    const int n = n0 + warp_n * 32 + nf * 8 + (lane & 3) * 2 + j;
                    const float v = c[mf][nf][i * 2 + j] + g_hb[b * H_DIM + n];
                    if (v > 0.0f) part += v * Ws[n];
                }
            }
            part += __shfl_xor_sync(0xffffffffu, part, 1);
            part += __shfl_xor_sync(0xffffffffu, part, 2);
            if ((lane & 3) == 0) atomicAdd(&g_attn_raw[m], part);
        }
    }
}

// ---------------- softmax ----------------
__global__ void softmax_kernel(const float* __restrict__ pe,
                               const void*  __restrict__ mask,
                               float* __restrict__ out, float scale) {
    const int b   = blockIdx.x;
    const int tid = threadIdx.x;
    __shared__ float red[256];
    const int mode = g_mask_mode;

    float v[2];
    #pragma unroll
    for (int q = 0; q < 2; q++) {
        const int s   = tid + q * 256;
        const int idx = b * S_LEN + s;
        float logit = scale * g_attn_raw[s * B_SZ + b] + pe[idx];
        bool msk;
        if      (mode == 1) msk = ((const unsigned char*)mask)[idx] != 0;
        else if (mode == 2) msk = ((const int*)mask)[idx] != 0;
        else if (mode == 3) msk = ((const float*)mask)[idx] != 0.0f;
        else                msk = false;
        v[q] = msk ? -1e12f : logit;
    }
    float mx = fmaxf(v[0], v[1]);
    red[tid] = mx; __syncthreads();
    #pragma unroll
    for (int o = 128; o; o >>= 1) {
        if (tid < o) red[tid] = fmaxf(red[tid], red[tid + o]);
        __syncthreads();
    }
    mx = red[0]; __syncthreads();
    const float e0 = __expf(v[0] - mx);
    const float e1 = __expf(v[1] - mx);
    red[tid] = e0 + e1; __syncthreads();
    #pragma unroll
    for (int o = 128; o; o >>= 1) {
        if (tid < o) red[tid] += red[tid + o];
        __syncthreads();
    }
    const float inv = 1.0f / red[0];
    out[b * S_LEN + tid]       = e0 * inv;
    out[b * S_LEN + tid + 256] = e1 * inv;
}

// ---------------- launch ----------------
extern "C" void kernel_launch(void* const* d_in, const int* in_sizes, int n_in,
                              void* d_out, int out_size) {
    const float* hidden = (const float*)d_in[0];
    const float* enc    = (const float*)d_in[1];
    const float* pe     = (const float*)d_in[2];
    const void*  mask   =               d_in[3];
    const float* Wa     = (const float*)d_in[4];
    const float* ba     = (const float*)d_in[5];
    const float* Ws     = (const float*)d_in[6];
    float* out = (float*)d_out;

    const float scale = (float)(log(512.0) / sqrt(1024.0));

    static int smem_set = 0;
    if (!smem_set) {
        cudaFuncSetAttribute(gemm_kernel, cudaFuncAttributeMaxDynamicSharedMemorySize, GSMEM);
        smem_set = 1;
    }

    init_kernel<<<256, 256>>>((const unsigned char*)mask, ba, Wa);   // 0
    convert_enc<<<4096, 256>>>(enc);                                  // 1
    hb_kernel<<<dim3(64, 8), 256>>>(hidden, Wa);                      // 2
    gemm_kernel<<<dim3(NDIM / BN, M_TOT / BM), 256, GSMEM>>>(Ws);     // 3  <- profiled slot
    softmax_kernel<<<B_SZ, 256>>>(pe, mask, out, scale);              // 4
}